// round 2
// baseline (speedup 1.0000x reference)
#include <cuda_runtime.h>
#include <math.h>

#define B_SZ 2048
#define L_SZ 64
#define D_SZ 256
#define U_SZ 512

typedef unsigned long long u64;

// Packed fp32x2 FMA (sm_103a): two independent fp32 FMAs per instruction slot.
#define FMA2(d, a, b, c) \
    asm("fma.rn.f32x2 %0, %1, %2, %3;" : "=l"(d) : "l"(a), "l"(b), "l"(c))
#define PACK2(d, lo, hi) \
    asm("mov.b64 %0, {%1, %2};" : "=l"(d) : "f"(lo), "f"(hi))
#define UNPACK2(lo, hi, s) \
    asm("mov.b64 {%0, %1}, %2;" : "=f"(lo), "=f"(hi) : "l"(s))

// Scratch for proj_h(+b1+b2): [B, U] fp32 = 4 MB (device global: allocation-free)
__device__ float g_ph[B_SZ * U_SZ];

// ---------------------------------------------------------------------------
// Kernel 1: g_ph[b][u] = hidden[b,:] . W2[:,u] + b1[u] + b2[u]
// ---------------------------------------------------------------------------
__global__ void proj_h_kernel(const float* __restrict__ hidden,
                              const float* __restrict__ W2,
                              const float* __restrict__ b1,
                              const float* __restrict__ b2)
{
    __shared__ float As[16][65];
    __shared__ float Bs[16][68];

    const int tid  = threadIdx.x;
    const int row0 = blockIdx.y * 64;
    const int col0 = blockIdx.x * 64;
    const int tr   = tid >> 4;
    const int tc   = tid & 15;

    float acc[4][4];
#pragma unroll
    for (int i = 0; i < 4; ++i)
#pragma unroll
        for (int j = 0; j < 4; ++j) acc[i][j] = 0.f;

    for (int k0 = 0; k0 < U_SZ; k0 += 16) {
#pragma unroll
        for (int t = 0; t < 4; ++t) {
            int idx = tid + 256 * t;
            int k = idx & 15;
            int m = idx >> 4;
            As[k][m] = hidden[(size_t)(row0 + m) * U_SZ + k0 + k];
        }
#pragma unroll
        for (int t = 0; t < 4; ++t) {
            int idx = tid + 256 * t;
            int n = idx & 63;
            int k = idx >> 6;
            Bs[k][n] = W2[(size_t)(k0 + k) * U_SZ + col0 + n];
        }
        __syncthreads();

#pragma unroll
        for (int k = 0; k < 16; ++k) {
            float a[4], bb[4];
#pragma unroll
            for (int i = 0; i < 4; ++i) a[i] = As[k][tr * 4 + i];
#pragma unroll
            for (int j = 0; j < 4; ++j) bb[j] = Bs[k][tc * 4 + j];
#pragma unroll
            for (int i = 0; i < 4; ++i)
#pragma unroll
                for (int j = 0; j < 4; ++j)
                    acc[i][j] = fmaf(a[i], bb[j], acc[i][j]);
        }
        __syncthreads();
    }

#pragma unroll
    for (int i = 0; i < 4; ++i) {
        int m = row0 + tr * 4 + i;
#pragma unroll
        for (int j = 0; j < 4; ++j) {
            int n = col0 + tc * 4 + j;
            g_ph[(size_t)m * U_SZ + n] = acc[i][j] + b1[n] + b2[n];
        }
    }
}

// ---------------------------------------------------------------------------
// Kernel 2: fused attention per batch row b (one CTA each).
// GEMM micro-kernel now uses packed fp32x2 FMA, paired over the K (d) dim:
//   a-pair = (F[l,d], F[l,d+1])   -> free LDS.64 from smem
//   b-pair = (W1[d,u], W1[d+1,u]) -> 4 packs / 2-d step
// Arithmetic bit-identical to scalar version.
// ---------------------------------------------------------------------------
__global__ void __launch_bounds__(256, 2)
attn_kernel(const float* __restrict__ features,
            const float* __restrict__ W1,
            const float* __restrict__ V,
            float* __restrict__ ctx_out,   // [B, 256] or null
            float* __restrict__ w_out)     // [B, 64]  or null
{
    extern __shared__ float Fs[];          // 64 x 256 fp32 = 64 KB
    __shared__ float ph_s[U_SZ];
    __shared__ float V_s[U_SZ];
    __shared__ float w_s[L_SZ];
    __shared__ float red[4];

    const int b   = blockIdx.x;
    const int tid = threadIdx.x;
    const int tx  = tid & 31;
    const int ty  = tid >> 5;

    // Stage features[b] (coalesced float4)
    {
        const float4* fsrc = reinterpret_cast<const float4*>(
            features + (size_t)b * L_SZ * D_SZ);
        float4* fdst = reinterpret_cast<float4*>(Fs);
#pragma unroll
        for (int i = 0; i < 16; ++i)
            fdst[tid + 256 * i] = fsrc[tid + 256 * i];
    }
    ph_s[tid]       = g_ph[(size_t)b * U_SZ + tid];
    ph_s[tid + 256] = g_ph[(size_t)b * U_SZ + tid + 256];
    V_s[tid]        = V[tid];
    V_s[tid + 256]  = V[tid + 256];
    __syncthreads();

    const float* frow = Fs + ty * 8 * D_SZ;

    float plog[8];
#pragma unroll
    for (int i = 0; i < 8; ++i) plog[i] = 0.f;

    for (int p = 0; p < 4; ++p) {
        const int u0 = p * 128 + tx * 4;

        u64 acc2[8][4];
#pragma unroll
        for (int i = 0; i < 8; ++i)
#pragma unroll
            for (int j = 0; j < 4; ++j) acc2[i][j] = 0ull;  // (0.f, 0.f)

        const float4* wp = reinterpret_cast<const float4*>(W1 + u0);

#pragma unroll 2
        for (int d = 0; d < D_SZ; d += 2) {
            float4 w0 = wp[(size_t)d * (U_SZ / 4)];
            float4 w1 = wp[(size_t)(d + 1) * (U_SZ / 4)];
            u64 wb[4];
            PACK2(wb[0], w0.x, w1.x);
            PACK2(wb[1], w0.y, w1.y);
            PACK2(wb[2], w0.z, w1.z);
            PACK2(wb[3], w0.w, w1.w);

            u64 fp2[8];
#pragma unroll
            for (int i = 0; i < 8; ++i)
                fp2[i] = *reinterpret_cast<const u64*>(frow + i * D_SZ + d);

#pragma unroll
            for (int i = 0; i < 8; ++i)
#pragma unroll
                for (int j = 0; j < 4; ++j)
                    FMA2(acc2[i][j], fp2[i], wb[j], acc2[i][j]);
        }

        float phv[4], vv[4];
#pragma unroll
        for (int j = 0; j < 4; ++j) { phv[j] = ph_s[u0 + j]; vv[j] = V_s[u0 + j]; }
#pragma unroll
        for (int i = 0; i < 8; ++i)
#pragma unroll
            for (int j = 0; j < 4; ++j) {
                float lo, hi;
                UNPACK2(lo, hi, acc2[i][j]);
                float s = tanhf(lo + hi + phv[j]);
                plog[i] = fmaf(vv[j], s, plog[i]);
            }
    }

    // Reduce logits across lanes
#pragma unroll
    for (int i = 0; i < 8; ++i) {
        float v = plog[i];
#pragma unroll
        for (int off = 16; off; off >>= 1)
            v += __shfl_xor_sync(0xffffffffu, v, off);
        if (tx == 0) w_s[ty * 8 + i] = v;
    }
    __syncthreads();

    // Softmax over L=64 (bV is a constant shift -> softmax invariant)
    float lv = (tid < 64) ? w_s[tid] : -1e30f;
    float m = lv;
#pragma unroll
    for (int off = 16; off; off >>= 1)
        m = fmaxf(m, __shfl_xor_sync(0xffffffffu, m, off));
    if (tid == 0)  red[0] = m;
    if (tid == 32) red[1] = m;
    __syncthreads();
    const float mx = fmaxf(red[0], red[1]);
    float e = (tid < 64) ? expf(lv - mx) : 0.f;
    float s = e;
#pragma unroll
    for (int off = 16; off; off >>= 1)
        s += __shfl_xor_sync(0xffffffffu, s, off);
    if (tid == 0)  red[2] = s;
    if (tid == 32) red[3] = s;
    __syncthreads();
    const float inv = 1.f / (red[2] + red[3]);
    if (tid < 64) w_s[tid] = e * inv;
    __syncthreads();

    // Context: thread tid owns feature dim d = tid
    float c = 0.f;
#pragma unroll
    for (int l = 0; l < L_SZ; ++l)
        c = fmaf(w_s[l], Fs[l * D_SZ + tid], c);

    if (ctx_out) ctx_out[(size_t)b * D_SZ + tid] = c;
    if (w_out && tid < L_SZ) w_out[(size_t)b * L_SZ + tid] = w_s[tid];
}

// ---------------------------------------------------------------------------
extern "C" void kernel_launch(void* const* d_in, const int* in_sizes, int n_in,
                              void* d_out, int out_size)
{
    const float* features = (const float*)d_in[0];
    const float* hidden   = (const float*)d_in[1];
    const float* W1       = (const float*)d_in[2];
    const float* b1       = (const float*)d_in[3];
    const float* W2       = (const float*)d_in[4];
    const float* b2       = (const float*)d_in[5];
    const float* V        = (const float*)d_in[6];
    // d_in[7] = bV: softmax is shift-invariant, so it never affects outputs.

    float* out = (float*)d_out;
    float* ctx_out = nullptr;
    float* w_out   = nullptr;
    const int CTX_N = B_SZ * D_SZ;
    const int W_N   = B_SZ * L_SZ;
    if (out_size >= CTX_N + W_N) { ctx_out = out; w_out = out + CTX_N; }
    else if (out_size == CTX_N)  { ctx_out = out; }
    else if (out_size == W_N)    { w_out = out; }
    else                         { ctx_out = out; }

    dim3 g1(U_SZ / 64, B_SZ / 64);
    proj_h_kernel<<<g1, 256>>>(hidden, W2, b1, b2);

    cudaFuncSetAttribute(attn_kernel,
                         cudaFuncAttributeMaxDynamicSharedMemorySize, 65536);
    attn_kernel<<<B_SZ, 256, 65536>>>(features, W1, V, ctx_out, w_out);
}

// round 4
// speedup vs baseline: 3.8439x; 3.8439x over previous
#include <cuda_runtime.h>
#include <cuda_bf16.h>
#include <math.h>
#include <stdint.h>

#define B_SZ 2048
#define L_SZ 64
#define D_SZ 256
#define U_SZ 512

#define PITCH 264                     // bf16 elems per row (256 + 8 pad): conflict-free LDSM
#define CH_ROWS 32                    // u-rows per B chunk
#define N_CHUNKS 16                   // 512 / 32
#define CH_BYTES (CH_ROWS * PITCH * 2)   // 16896
#define A_BYTES (128 * PITCH * 2)        // 67584

// ---------------------------------------------------------------------------
// PTX helpers (base-PTX only: no 'a'-suffix features; compiles on compute_103)
// ---------------------------------------------------------------------------
__device__ __forceinline__ uint32_t smem_to_u32(const void* p) {
    uint32_t a;
    asm("{ .reg .u64 t; cvta.to.shared.u64 t, %1; cvt.u32.u64 %0, t; }"
        : "=r"(a) : "l"(p));
    return a;
}

#define MBARRIER_INIT(mb, c) \
    asm volatile("mbarrier.init.shared.b64 [%0], %1;" \
                 :: "r"((uint32_t)(mb)), "r"((uint32_t)(c)) : "memory")
#define MBARRIER_INVAL(mb) \
    asm volatile("mbarrier.inval.shared.b64 [%0];" :: "r"((uint32_t)(mb)) : "memory")
#define MBARRIER_EXPECT_TX(mb, bytes) \
    asm volatile("mbarrier.arrive.expect_tx.shared.b64 _, [%0], %1;" \
                 :: "r"((uint32_t)(mb)), "r"((uint32_t)(bytes)) : "memory")

#define MBARRIER_WAIT_PARITY(mb, ph) do { \
    uint32_t _mb = (uint32_t)(mb); uint32_t _p = (uint32_t)(ph); uint32_t _done; \
    asm volatile("{\n\t.reg .pred p;\n\t" \
        "mbarrier.try_wait.parity.acquire.cta.shared::cta.b64 p, [%1], %2;\n\t" \
        "selp.b32 %0, 1, 0, p;\n\t}" : "=r"(_done) : "r"(_mb), "r"(_p) : "memory"); \
    if (!_done) { \
        asm volatile("{\n\t.reg .pred P1;\n\t" \
            "WL_%=:\n\t" \
            "mbarrier.try_wait.parity.acquire.cta.shared::cta.b64 P1, [%0], %1, 0x989680;\n\t" \
            "@P1 bra.uni WD_%=;\n\t" \
            "bra.uni WL_%=;\n\t" \
            "WD_%=:\n\t}" :: "r"(_mb), "r"(_p) : "memory"); \
    } \
} while (0)

// 1D bulk async copy gmem -> smem (TMA engine; sm_90 base feature)
#define BULK_G2S(dst, src, sz, mb) \
    asm volatile("cp.async.bulk.shared::cluster.global.mbarrier::complete_tx::bytes " \
                 "[%0], [%1], %2, [%3];" \
                 :: "r"((uint32_t)(dst)), "l"(src), "r"((uint32_t)(sz)), \
                    "r"((uint32_t)(mb)) : "memory")

#define LDMX4(r0, r1, r2, r3, addr) \
    asm volatile("ldmatrix.sync.aligned.m8n8.x4.shared.b16 {%0,%1,%2,%3}, [%4];" \
                 : "=r"(r0), "=r"(r1), "=r"(r2), "=r"(r3) : "r"(addr))
#define LDMX2(r0, r1, addr) \
    asm volatile("ldmatrix.sync.aligned.m8n8.x2.shared.b16 {%0,%1}, [%2];" \
                 : "=r"(r0), "=r"(r1) : "r"(addr))

#define MMA16816(c, a0, a1, a2, a3, b0, b1) \
    asm volatile("mma.sync.aligned.m16n8k16.row.col.f32.bf16.bf16.f32 " \
                 "{%0,%1,%2,%3},{%4,%5,%6,%7},{%8,%9},{%0,%1,%2,%3};" \
                 : "+f"((c)[0]), "+f"((c)[1]), "+f"((c)[2]), "+f"((c)[3]) \
                 : "r"(a0), "r"(a1), "r"(a2), "r"(a3), "r"(b0), "r"(b1))

__device__ __forceinline__ float tanh_fast(float x) {
    // 1 - 2/(e^{2x}+1); saturates correctly for |x| large; abs err ~1e-7
    float e = __expf(2.f * x);
    return 1.f - __fdividef(2.f, e + 1.f);
}

// ---------------------------------------------------------------------------
// Device scratch (allocation-free)
// ---------------------------------------------------------------------------
__device__ float g_ph[B_SZ * U_SZ];
__device__ __align__(16) unsigned char g_w1t_hi[N_CHUNKS * CH_BYTES];
__device__ __align__(16) unsigned char g_w1t_lo[N_CHUNKS * CH_BYTES];

// ---------------------------------------------------------------------------
// Prep: W1[d][u] -> chunked W1^T (bf16 hi/lo), rows n=u%32, cols k=d, pitch 264
// ---------------------------------------------------------------------------
__global__ void prep_w1_kernel(const float* __restrict__ W1) {
    const int d = blockIdx.x;          // 0..255
    const int u = threadIdx.x;         // 0..511
    const float f = W1[(size_t)d * U_SZ + u];
    const __nv_bfloat16 hi = __float2bfloat16(f);
    const __nv_bfloat16 lo = __float2bfloat16(f - __bfloat162float(hi));
    const int chunk = u >> 5, n = u & 31;
    const size_t off = (size_t)chunk * CH_BYTES + ((size_t)n * PITCH + d) * 2;
    *(__nv_bfloat16*)(g_w1t_hi + off) = hi;
    *(__nv_bfloat16*)(g_w1t_lo + off) = lo;
}

// ---------------------------------------------------------------------------
// proj_h: g_ph[b][u] = hidden[b,:].W2[:,u] + b1[u] + b2[u]
// ---------------------------------------------------------------------------
__global__ void proj_h_kernel(const float* __restrict__ hidden,
                              const float* __restrict__ W2,
                              const float* __restrict__ b1,
                              const float* __restrict__ b2)
{
    __shared__ float As[16][65];
    __shared__ float Bs[16][68];
    const int tid  = threadIdx.x;
    const int row0 = blockIdx.y * 64;
    const int col0 = blockIdx.x * 64;
    const int tr   = tid >> 4;
    const int tc   = tid & 15;

    float acc[4][4];
#pragma unroll
    for (int i = 0; i < 4; ++i)
#pragma unroll
        for (int j = 0; j < 4; ++j) acc[i][j] = 0.f;

    for (int k0 = 0; k0 < U_SZ; k0 += 16) {
#pragma unroll
        for (int t = 0; t < 4; ++t) {
            int idx = tid + 256 * t;
            As[idx & 15][idx >> 4] =
                hidden[(size_t)(row0 + (idx >> 4)) * U_SZ + k0 + (idx & 15)];
        }
#pragma unroll
        for (int t = 0; t < 4; ++t) {
            int idx = tid + 256 * t;
            Bs[idx >> 6][idx & 63] =
                W2[(size_t)(k0 + (idx >> 6)) * U_SZ + col0 + (idx & 63)];
        }
        __syncthreads();
#pragma unroll
        for (int k = 0; k < 16; ++k) {
            float a[4], bb[4];
#pragma unroll
            for (int i = 0; i < 4; ++i) a[i] = As[k][tr * 4 + i];
#pragma unroll
            for (int j = 0; j < 4; ++j) bb[j] = Bs[k][tc * 4 + j];
#pragma unroll
            for (int i = 0; i < 4; ++i)
#pragma unroll
                for (int j = 0; j < 4; ++j) acc[i][j] = fmaf(a[i], bb[j], acc[i][j]);
        }
        __syncthreads();
    }
#pragma unroll
    for (int i = 0; i < 4; ++i)
#pragma unroll
        for (int j = 0; j < 4; ++j) {
            int n = col0 + tc * 4 + j;
            g_ph[(size_t)(row0 + tr * 4 + i) * U_SZ + n] = acc[i][j] + b1[n] + b2[n];
        }
}

// ---------------------------------------------------------------------------
// Main fused kernel: 1 CTA = 2 batches (M=128 rows), 8 warps x 16 rows.
// SMEM byte offsets:
static constexpr int SA_HI = 0;                       // 67584
static constexpr int SA_LO = 67584;                   // 67584
static constexpr int SB    = 135168;                  // 2 bufs x (hi+lo) = 67584
static constexpr int BUF_STRIDE = 2 * CH_BYTES;       // 33792
static constexpr int SPH   = 202752;                  // 4096
static constexpr int SV    = 206848;                  // 2048
static constexpr int SW    = 208896;                  // 512 (logits -> weights, 128)
static constexpr int SRED  = 209408;                  // 32
static constexpr int SMBAR = 209440;                  // 2 x 8B
static constexpr int SMEM_TOTAL = 209472;
// ---------------------------------------------------------------------------
__global__ void __launch_bounds__(256, 1)
attn_mma_kernel(const float* __restrict__ features,
                const float* __restrict__ V,
                float* __restrict__ ctx_out,
                float* __restrict__ w_out)
{
    extern __shared__ __align__(1024) char smem[];
    const uint32_t smem_u = smem_to_u32(smem);
    const int tid  = threadIdx.x;
    const int wid  = tid >> 5;
    const int lane = tid & 31;
    const int b0   = blockIdx.x * 2;

    float* ph_s  = (float*)(smem + SPH);
    float* V_s   = (float*)(smem + SV);
    float* w_s   = (float*)(smem + SW);
    float* red_s = (float*)(smem + SRED);

    // ---- mbarriers + kick off first two B-chunk bulk copies (TMA path) ----
    if (tid == 0) {
        MBARRIER_INIT(smem_u + SMBAR, 1);
        MBARRIER_INIT(smem_u + SMBAR + 8, 1);
#pragma unroll
        for (int c = 0; c < 2; ++c) {
            const uint32_t mb = smem_u + SMBAR + 8 * c;
            const uint32_t bh = smem_u + SB + c * BUF_STRIDE;
            MBARRIER_EXPECT_TX(mb, 2 * CH_BYTES);
            BULK_G2S(bh,            g_w1t_hi + (size_t)c * CH_BYTES, CH_BYTES, mb);
            BULK_G2S(bh + CH_BYTES, g_w1t_lo + (size_t)c * CH_BYTES, CH_BYTES, mb);
        }
    }

    // ---- Stage features[b0..b0+1] as bf16 hi/lo (padded rows) ----
    {
        const float4* fsrc = (const float4*)(features + (size_t)b0 * L_SZ * D_SZ);
#pragma unroll 4
        for (int t = 0; t < 32; ++t) {
            const int idx = tid + 256 * t;       // 0..8191
            const int row = idx >> 6;
            const int d   = (idx & 63) * 4;
            const float4 v = fsrc[idx];
            __nv_bfloat162 h0 = __float22bfloat162_rn(make_float2(v.x, v.y));
            __nv_bfloat162 h1 = __float22bfloat162_rn(make_float2(v.z, v.w));
            __nv_bfloat162 l0 = __float22bfloat162_rn(make_float2(
                v.x - __bfloat162float(h0.x), v.y - __bfloat162float(h0.y)));
            __nv_bfloat162 l1 = __float22bfloat162_rn(make_float2(
                v.z - __bfloat162float(h1.x), v.w - __bfloat162float(h1.y)));
            const uint32_t off = ((uint32_t)row * PITCH + d) * 2;   // 8B aligned
            *(uint2*)(smem + SA_HI + off) =
                make_uint2(*(uint32_t*)&h0, *(uint32_t*)&h1);
            *(uint2*)(smem + SA_LO + off) =
                make_uint2(*(uint32_t*)&l0, *(uint32_t*)&l1);
        }
    }
#pragma unroll
    for (int t = 0; t < 4; ++t)
        ph_s[tid + 256 * t] = g_ph[(size_t)b0 * U_SZ + tid + 256 * t];
    V_s[tid]       = V[tid];
    V_s[tid + 256] = V[tid + 256];
    __syncthreads();

    // ---- per-lane ldmatrix address components ----
    const int m0 = wid * 16;                        // warp's first row
    const uint32_t a_row = (uint32_t)(m0 + (lane & 7) + ((lane >> 3) & 1) * 8);
    const uint32_t a_off = (a_row * PITCH + ((uint32_t)(lane >> 4)) * 8) * 2;
    const uint32_t b_off = (((uint32_t)(lane & 7)) * PITCH +
                            ((uint32_t)((lane >> 3) & 1)) * 8) * 2;
    const int phb = (wid >> 2) * U_SZ;              // batch base into ph_s

    float pl0 = 0.f, pl1 = 0.f;                     // logit partials (2 rows/thread)

    // ==================== chunk loop ====================
    for (int c = 0; c < N_CHUNKS; ++c) {
        const uint32_t mb = smem_u + SMBAR + 8 * (c & 1);
        MBARRIER_WAIT_PARITY(mb, (c >> 1) & 1);

        const uint32_t bh = smem_u + SB + (c & 1) * BUF_STRIDE;
        const uint32_t bl = bh + CH_BYTES;

        float acc[4][4];
#pragma unroll
        for (int j = 0; j < 4; ++j)
#pragma unroll
            for (int r = 0; r < 4; ++r) acc[j][r] = 0.f;

#pragma unroll 4
        for (int kk = 0; kk < 16; ++kk) {
            const uint32_t koff = (uint32_t)kk * 32;
            uint32_t ah0, ah1, ah2, ah3, al0, al1, al2, al3;
            LDMX4(ah0, ah1, ah2, ah3, smem_u + SA_HI + a_off + koff);
            LDMX4(al0, al1, al2, al3, smem_u + SA_LO + a_off + koff);
#pragma unroll
            for (int j = 0; j < 4; ++j) {
                const uint32_t jb = b_off + (uint32_t)j * (8 * PITCH * 2) + koff;
                uint32_t bh0, bh1, bl0, bl1;
                LDMX2(bh0, bh1, bh + jb);
                LDMX2(bl0, bl1, bl + jb);
                MMA16816(acc[j], ah0, ah1, ah2, ah3, bh0, bh1);  // hh
                MMA16816(acc[j], ah0, ah1, ah2, ah3, bl0, bl1);  // hl
                MMA16816(acc[j], al0, al1, al2, al3, bh0, bh1);  // lh
            }
        }

        // fused epilogue for this chunk's u-columns
#pragma unroll
        for (int j = 0; j < 4; ++j) {
            const int u = c * 32 + j * 8 + (lane & 3) * 2;
            const float ph0 = ph_s[phb + u],     vv0 = V_s[u];
            const float ph1 = ph_s[phb + u + 1], vv1 = V_s[u + 1];
            pl0 = fmaf(vv0, tanh_fast(acc[j][0] + ph0), pl0);
            pl0 = fmaf(vv1, tanh_fast(acc[j][1] + ph1), pl0);
            pl1 = fmaf(vv0, tanh_fast(acc[j][2] + ph0), pl1);
            pl1 = fmaf(vv1, tanh_fast(acc[j][3] + ph1), pl1);
        }

        __syncthreads();   // all warps done with buffer (c&1) before refill
        if (tid == 0 && c + 2 < N_CHUNKS) {
            const int cn = c + 2;
            const uint32_t mbn = smem_u + SMBAR + 8 * (cn & 1);
            const uint32_t bhn = smem_u + SB + (cn & 1) * BUF_STRIDE;
            MBARRIER_EXPECT_TX(mbn, 2 * CH_BYTES);
            BULK_G2S(bhn,            g_w1t_hi + (size_t)cn * CH_BYTES, CH_BYTES, mbn);
            BULK_G2S(bhn + CH_BYTES, g_w1t_lo + (size_t)cn * CH_BYTES, CH_BYTES, mbn);
        }
    }

    // ---- reduce logit partials across the 4 lanes sharing a row ----
    pl0 += __shfl_xor_sync(0xffffffffu, pl0, 1);
    pl0 += __shfl_xor_sync(0xffffffffu, pl0, 2);
    pl1 += __shfl_xor_sync(0xffffffffu, pl1, 1);
    pl1 += __shfl_xor_sync(0xffffffffu, pl1, 2);
    if ((lane & 3) == 0) {
        w_s[m0 + (lane >> 2)]     = pl0;
        w_s[m0 + 8 + (lane >> 2)] = pl1;
    }
    __syncthreads();

    // ---- softmax per batch over L=64 (warps 0-3; bV shift-invariant) ----
    {
        const bool act = wid < 4;
        const int bb = (wid >> 1) & 1;
        const int li = (wid & 1) * 32 + lane;
        float lv = act ? w_s[bb * 64 + li] : -1e30f;
        float m = lv;
#pragma unroll
        for (int off = 16; off; off >>= 1)
            m = fmaxf(m, __shfl_xor_sync(0xffffffffu, m, off));
        if (act && lane == 0) red_s[wid] = m;
        __syncthreads();
        const float mx = fmaxf(red_s[bb * 2], red_s[bb * 2 + 1]);
        float e = act ? expf(lv - mx) : 0.f;
        float s = e;
#pragma unroll
        for (int off = 16; off; off >>= 1)
            s += __shfl_xor_sync(0xffffffffu, s, off);
        if (act && lane == 0) red_s[4 + wid] = s;
        __syncthreads();
        if (act) w_s[bb * 64 + li] = e / (red_s[4 + bb * 2] + red_s[5 + bb * 2]);
        __syncthreads();
    }

    // ---- context: ctx[bb,d] = sum_l w[bb,l] * (F_hi + F_lo)[bb*64+l, d] ----
    {
        const int d = tid;  // 0..255
#pragma unroll
        for (int bb = 0; bb < 2; ++bb) {
            float cacc = 0.f;
#pragma unroll 8
            for (int l = 0; l < 64; ++l) {
                const uint32_t off = (((uint32_t)(bb * 64 + l)) * PITCH + d) * 2;
                const float hi = __bfloat162float(*(const __nv_bfloat16*)(smem + SA_HI + off));
                const float lo = __bfloat162float(*(const __nv_bfloat16*)(smem + SA_LO + off));
                cacc = fmaf(w_s[bb * 64 + l], hi + lo, cacc);
            }
            if (ctx_out) ctx_out[(size_t)(b0 + bb) * D_SZ + d] = cacc;
        }
        if (w_out && tid < 128) w_out[(size_t)b0 * L_SZ + tid] = w_s[tid];
    }

    __syncthreads();
    if (tid == 0) {
        MBARRIER_INVAL(smem_u + SMBAR);
        MBARRIER_INVAL(smem_u + SMBAR + 8);
    }
}

// ---------------------------------------------------------------------------
extern "C" void kernel_launch(void* const* d_in, const int* in_sizes, int n_in,
                              void* d_out, int out_size)
{
    const float* features = (const float*)d_in[0];
    const float* hidden   = (const float*)d_in[1];
    const float* W1       = (const float*)d_in[2];
    const float* b1       = (const float*)d_in[3];
    const float* W2       = (const float*)d_in[4];
    const float* b2       = (const float*)d_in[5];
    const float* V        = (const float*)d_in[6];
    // d_in[7] = bV: softmax shift-invariant -> no output effect.

    float* out = (float*)d_out;
    float* ctx_out = nullptr;
    float* w_out   = nullptr;
    const int CTX_N = B_SZ * D_SZ;
    const int W_N   = B_SZ * L_SZ;
    if (out_size >= CTX_N + W_N) { ctx_out = out; w_out = out + CTX_N; }
    else if (out_size == CTX_N)  { ctx_out = out; }
    else if (out_size == W_N)    { w_out = out; }
    else                         { ctx_out = out; }

    prep_w1_kernel<<<D_SZ, U_SZ>>>(W1);

    dim3 g1(U_SZ / 64, B_SZ / 64);
    proj_h_kernel<<<g1, 256>>>(hidden, W2, b1, b2);

    cudaFuncSetAttribute(attn_mma_kernel,
                         cudaFuncAttributeMaxDynamicSharedMemorySize, SMEM_TOTAL);
    attn_mma_kernel<<<B_SZ / 2, 256, SMEM_TOTAL>>>(features, V, ctx_out, w_out);
}

// round 5
// speedup vs baseline: 3.9823x; 1.0360x over previous
#include <cuda_runtime.h>
#include <cuda_bf16.h>
#include <math.h>
#include <stdint.h>

#define B_SZ 2048
#define L_SZ 64
#define D_SZ 256
#define U_SZ 512

#define PITCH 264                     // bf16 elems per row (256 + 8 pad): conflict-free LDSM
#define CH_ROWS 32                    // u-rows per B chunk
#define N_CHUNKS 16                   // 512 / 32
#define CH_BYTES (CH_ROWS * PITCH * 2)   // 16896

// ---------------------------------------------------------------------------
// PTX helpers (base-PTX only; compiles under compute_103)
// ---------------------------------------------------------------------------
__device__ __forceinline__ uint32_t smem_to_u32(const void* p) {
    uint32_t a;
    asm("{ .reg .u64 t; cvta.to.shared.u64 t, %1; cvt.u32.u64 %0, t; }"
        : "=r"(a) : "l"(p));
    return a;
}

#define MBARRIER_INIT(mb, c) \
    asm volatile("mbarrier.init.shared.b64 [%0], %1;" \
                 :: "r"((uint32_t)(mb)), "r"((uint32_t)(c)) : "memory")
#define MBARRIER_INVAL(mb) \
    asm volatile("mbarrier.inval.shared.b64 [%0];" :: "r"((uint32_t)(mb)) : "memory")
#define MBARRIER_EXPECT_TX(mb, bytes) \
    asm volatile("mbarrier.arrive.expect_tx.shared.b64 _, [%0], %1;" \
                 :: "r"((uint32_t)(mb)), "r"((uint32_t)(bytes)) : "memory")

#define MBARRIER_WAIT_PARITY(mb, ph) do { \
    uint32_t _mb = (uint32_t)(mb); uint32_t _p = (uint32_t)(ph); uint32_t _done; \
    asm volatile("{\n\t.reg .pred p;\n\t" \
        "mbarrier.try_wait.parity.acquire.cta.shared::cta.b64 p, [%1], %2;\n\t" \
        "selp.b32 %0, 1, 0, p;\n\t}" : "=r"(_done) : "r"(_mb), "r"(_p) : "memory"); \
    if (!_done) { \
        asm volatile("{\n\t.reg .pred P1;\n\t" \
            "WL_%=:\n\t" \
            "mbarrier.try_wait.parity.acquire.cta.shared::cta.b64 P1, [%0], %1, 0x989680;\n\t" \
            "@P1 bra.uni WD_%=;\n\t" \
            "bra.uni WL_%=;\n\t" \
            "WD_%=:\n\t}" :: "r"(_mb), "r"(_p) : "memory"); \
    } \
} while (0)

// 1D bulk async copy gmem -> smem (TMA engine)
#define BULK_G2S(dst, src, sz, mb) \
    asm volatile("cp.async.bulk.shared::cluster.global.mbarrier::complete_tx::bytes " \
                 "[%0], [%1], %2, [%3];" \
                 :: "r"((uint32_t)(dst)), "l"(src), "r"((uint32_t)(sz)), \
                    "r"((uint32_t)(mb)) : "memory")

#define LDMX4(r0, r1, r2, r3, addr) \
    asm volatile("ldmatrix.sync.aligned.m8n8.x4.shared.b16 {%0,%1,%2,%3}, [%4];" \
                 : "=r"(r0), "=r"(r1), "=r"(r2), "=r"(r3) : "r"(addr))

#define MMA16816(c, a0, a1, a2, a3, b0, b1) \
    asm volatile("mma.sync.aligned.m16n8k16.row.col.f32.bf16.bf16.f32 " \
                 "{%0,%1,%2,%3},{%4,%5,%6,%7},{%8,%9},{%0,%1,%2,%3};" \
                 : "+f"((c)[0]), "+f"((c)[1]), "+f"((c)[2]), "+f"((c)[3]) \
                 : "r"(a0), "r"(a1), "r"(a2), "r"(a3), "r"(b0), "r"(b1))

__device__ __forceinline__ float tanh_fast(float x) {
    float e = __expf(2.f * x);
    return 1.f - __fdividef(2.f, e + 1.f);
}

// ---------------------------------------------------------------------------
// Device scratch (allocation-free)
// ---------------------------------------------------------------------------
__device__ float g_ph[B_SZ * U_SZ];
__device__ __align__(16) unsigned char g_w1t_hi[N_CHUNKS * CH_BYTES];
__device__ __align__(16) unsigned char g_w1t_lo[N_CHUNKS * CH_BYTES];

// ---------------------------------------------------------------------------
// Prep: W1[d][u] -> chunked W1^T (bf16 hi/lo), rows n=u%32, cols k=d, pitch 264
// ---------------------------------------------------------------------------
__global__ void prep_w1_kernel(const float* __restrict__ W1) {
    const int d = blockIdx.x;
    const int u = threadIdx.x;
    const float f = W1[(size_t)d * U_SZ + u];
    const __nv_bfloat16 hi = __float2bfloat16(f);
    const __nv_bfloat16 lo = __float2bfloat16(f - __bfloat162float(hi));
    const int chunk = u >> 5, n = u & 31;
    const size_t off = (size_t)chunk * CH_BYTES + ((size_t)n * PITCH + d) * 2;
    *(__nv_bfloat16*)(g_w1t_hi + off) = hi;
    *(__nv_bfloat16*)(g_w1t_lo + off) = lo;
}

// ---------------------------------------------------------------------------
// proj_h: g_ph[b][u] = hidden[b,:].W2[:,u] + b1[u] + b2[u]
// ---------------------------------------------------------------------------
__global__ void proj_h_kernel(const float* __restrict__ hidden,
                              const float* __restrict__ W2,
                              const float* __restrict__ b1,
                              const float* __restrict__ b2)
{
    __shared__ float As[16][65];
    __shared__ float Bs[16][68];
    const int tid  = threadIdx.x;
    const int row0 = blockIdx.y * 64;
    const int col0 = blockIdx.x * 64;
    const int tr   = tid >> 4;
    const int tc   = tid & 15;

    float acc[4][4];
#pragma unroll
    for (int i = 0; i < 4; ++i)
#pragma unroll
        for (int j = 0; j < 4; ++j) acc[i][j] = 0.f;

    for (int k0 = 0; k0 < U_SZ; k0 += 16) {
#pragma unroll
        for (int t = 0; t < 4; ++t) {
            int idx = tid + 256 * t;
            As[idx & 15][idx >> 4] =
                hidden[(size_t)(row0 + (idx >> 4)) * U_SZ + k0 + (idx & 15)];
        }
#pragma unroll
        for (int t = 0; t < 4; ++t) {
            int idx = tid + 256 * t;
            Bs[idx >> 6][idx & 63] =
                W2[(size_t)(k0 + (idx >> 6)) * U_SZ + col0 + (idx & 63)];
        }
        __syncthreads();
#pragma unroll
        for (int k = 0; k < 16; ++k) {
            float a[4], bb[4];
#pragma unroll
            for (int i = 0; i < 4; ++i) a[i] = As[k][tr * 4 + i];
#pragma unroll
            for (int j = 0; j < 4; ++j) bb[j] = Bs[k][tc * 4 + j];
#pragma unroll
            for (int i = 0; i < 4; ++i)
#pragma unroll
                for (int j = 0; j < 4; ++j) acc[i][j] = fmaf(a[i], bb[j], acc[i][j]);
        }
        __syncthreads();
    }
#pragma unroll
    for (int i = 0; i < 4; ++i)
#pragma unroll
        for (int j = 0; j < 4; ++j) {
            int n = col0 + tc * 4 + j;
            g_ph[(size_t)(row0 + tr * 4 + i) * U_SZ + n] = acc[i][j] + b1[n] + b2[n];
        }
}

// ---------------------------------------------------------------------------
// Main fused kernel: 1 CTA = 2 batches (M=128 rows), 8 warps x 16 rows.
// A fragments live in REGISTERS for the whole chunk loop (loaded once).
// SMEM byte offsets:
static constexpr int SA_HI = 0;                       // 67584
static constexpr int SA_LO = 67584;                   // 67584
static constexpr int SB    = 135168;                  // 2 bufs x (hi+lo)
static constexpr int BUF_STRIDE = 2 * CH_BYTES;       // 33792
static constexpr int SPH   = 202752;                  // 4096
static constexpr int SV    = 206848;                  // 2048
static constexpr int SW    = 208896;                  // 512
static constexpr int SRED  = 209408;                  // 32
static constexpr int SMBAR = 209440;                  // 2 x 8B
static constexpr int SMEM_TOTAL = 209472;
// ---------------------------------------------------------------------------
__global__ void __launch_bounds__(256, 1)
attn_mma_kernel(const float* __restrict__ features,
                const float* __restrict__ V,
                float* __restrict__ ctx_out,
                float* __restrict__ w_out)
{
    extern __shared__ __align__(1024) char smem[];
    const uint32_t smem_u = smem_to_u32(smem);
    const int tid  = threadIdx.x;
    const int wid  = tid >> 5;
    const int lane = tid & 31;
    const int b0   = blockIdx.x * 2;

    float* ph_s  = (float*)(smem + SPH);
    float* V_s   = (float*)(smem + SV);
    float* w_s   = (float*)(smem + SW);
    float* red_s = (float*)(smem + SRED);

    // ---- mbarriers + kick off first two B-chunk bulk copies ----
    if (tid == 0) {
        MBARRIER_INIT(smem_u + SMBAR, 1);
        MBARRIER_INIT(smem_u + SMBAR + 8, 1);
#pragma unroll
        for (int c = 0; c < 2; ++c) {
            const uint32_t mb = smem_u + SMBAR + 8 * c;
            const uint32_t bh = smem_u + SB + c * BUF_STRIDE;
            MBARRIER_EXPECT_TX(mb, 2 * CH_BYTES);
            BULK_G2S(bh,            g_w1t_hi + (size_t)c * CH_BYTES, CH_BYTES, mb);
            BULK_G2S(bh + CH_BYTES, g_w1t_lo + (size_t)c * CH_BYTES, CH_BYTES, mb);
        }
    }

    // ---- Stage features[b0..b0+1] as bf16 hi/lo (padded rows) ----
    {
        const float4* fsrc = (const float4*)(features + (size_t)b0 * L_SZ * D_SZ);
#pragma unroll 4
        for (int t = 0; t < 32; ++t) {
            const int idx = tid + 256 * t;
            const int row = idx >> 6;
            const int d   = (idx & 63) * 4;
            const float4 v = fsrc[idx];
            __nv_bfloat162 h0 = __float22bfloat162_rn(make_float2(v.x, v.y));
            __nv_bfloat162 h1 = __float22bfloat162_rn(make_float2(v.z, v.w));
            __nv_bfloat162 l0 = __float22bfloat162_rn(make_float2(
                v.x - __bfloat162float(h0.x), v.y - __bfloat162float(h0.y)));
            __nv_bfloat162 l1 = __float22bfloat162_rn(make_float2(
                v.z - __bfloat162float(h1.x), v.w - __bfloat162float(h1.y)));
            const uint32_t off = ((uint32_t)row * PITCH + d) * 2;
            *(uint2*)(smem + SA_HI + off) =
                make_uint2(*(uint32_t*)&h0, *(uint32_t*)&h1);
            *(uint2*)(smem + SA_LO + off) =
                make_uint2(*(uint32_t*)&l0, *(uint32_t*)&l1);
        }
    }
#pragma unroll
    for (int t = 0; t < 4; ++t)
        ph_s[tid + 256 * t] = g_ph[(size_t)b0 * U_SZ + tid + 256 * t];
    V_s[tid]       = V[tid];
    V_s[tid + 256] = V[tid + 256];
    __syncthreads();

    // ---- ldmatrix address components ----
    const int m0 = wid * 16;
    const uint32_t a_row = (uint32_t)(m0 + (lane & 7) + ((lane >> 3) & 1) * 8);
    const uint32_t a_off = (a_row * PITCH + ((uint32_t)(lane >> 4)) * 8) * 2;
    // B x4: n16 x k16 per load. lanes0-7: n0-7,k0; 8-15: n0-7,k8; 16-23: n8-15,k0; 24-31: n8-15,k8
    const uint32_t b4_off = (((uint32_t)(lane & 7) + (((uint32_t)lane >> 4) & 1) * 8) * PITCH) * 2
                          + (((uint32_t)lane >> 3) & 1) * 16;
    const int phb = (wid >> 2) * U_SZ;

    // ---- Preload ALL A fragments into registers (once, not per chunk) ----
    uint32_t ah[16][4], al[16][4];
#pragma unroll
    for (int kk = 0; kk < 16; ++kk) {
        const uint32_t koff = (uint32_t)kk * 32;
        LDMX4(ah[kk][0], ah[kk][1], ah[kk][2], ah[kk][3],
              smem_u + SA_HI + a_off + koff);
        LDMX4(al[kk][0], al[kk][1], al[kk][2], al[kk][3],
              smem_u + SA_LO + a_off + koff);
    }

    float pl0 = 0.f, pl1 = 0.f;

    // ==================== chunk loop ====================
    for (int c = 0; c < N_CHUNKS; ++c) {
        const uint32_t mb = smem_u + SMBAR + 8 * (c & 1);
        MBARRIER_WAIT_PARITY(mb, (c >> 1) & 1);

        const uint32_t bh = smem_u + SB + (c & 1) * BUF_STRIDE;
        const uint32_t bl = bh + CH_BYTES;

        float acc[4][4];
#pragma unroll
        for (int j = 0; j < 4; ++j)
#pragma unroll
            for (int r = 0; r < 4; ++r) acc[j][r] = 0.f;

#pragma unroll
        for (int kk = 0; kk < 16; ++kk) {
            const uint32_t koff = (uint32_t)kk * 32;
#pragma unroll
            for (int j2 = 0; j2 < 2; ++j2) {
                const uint32_t jb = b4_off + (uint32_t)j2 * (16 * PITCH * 2) + koff;
                uint32_t bh0, bh1, bh2, bh3, bl0, bl1, bl2, bl3;
                LDMX4(bh0, bh1, bh2, bh3, bh + jb);
                LDMX4(bl0, bl1, bl2, bl3, bl + jb);
                MMA16816(acc[j2 * 2], ah[kk][0], ah[kk][1], ah[kk][2], ah[kk][3], bh0, bh1);
                MMA16816(acc[j2 * 2], ah[kk][0], ah[kk][1], ah[kk][2], ah[kk][3], bl0, bl1);
                MMA16816(acc[j2 * 2], al[kk][0], al[kk][1], al[kk][2], al[kk][3], bh0, bh1);
                MMA16816(acc[j2 * 2 + 1], ah[kk][0], ah[kk][1], ah[kk][2], ah[kk][3], bh2, bh3);
                MMA16816(acc[j2 * 2 + 1], ah[kk][0], ah[kk][1], ah[kk][2], ah[kk][3], bl2, bl3);
                MMA16816(acc[j2 * 2 + 1], al[kk][0], al[kk][1], al[kk][2], al[kk][3], bh2, bh3);
            }
        }

        // fused epilogue for this chunk's u-columns
#pragma unroll
        for (int j = 0; j < 4; ++j) {
            const int u = c * 32 + j * 8 + (lane & 3) * 2;
            const float ph0 = ph_s[phb + u],     vv0 = V_s[u];
            const float ph1 = ph_s[phb + u + 1], vv1 = V_s[u + 1];
            pl0 = fmaf(vv0, tanh_fast(acc[j][0] + ph0), pl0);
            pl0 = fmaf(vv1, tanh_fast(acc[j][1] + ph1), pl0);
            pl1 = fmaf(vv0, tanh_fast(acc[j][2] + ph0), pl1);
            pl1 = fmaf(vv1, tanh_fast(acc[j][3] + ph1), pl1);
        }

        __syncthreads();   // all warps done with buffer (c&1) before refill
        if (tid == 0 && c + 2 < N_CHUNKS) {
            const int cn = c + 2;
            const uint32_t mbn = smem_u + SMBAR + 8 * (cn & 1);
            const uint32_t bhn = smem_u + SB + (cn & 1) * BUF_STRIDE;
            MBARRIER_EXPECT_TX(mbn, 2 * CH_BYTES);
            BULK_G2S(bhn,            g_w1t_hi + (size_t)cn * CH_BYTES, CH_BYTES, mbn);
            BULK_G2S(bhn + CH_BYTES, g_w1t_lo + (size_t)cn * CH_BYTES, CH_BYTES, mbn);
        }
    }

    // ---- reduce logit partials across the 4 lanes sharing a row ----
    pl0 += __shfl_xor_sync(0xffffffffu, pl0, 1);
    pl0 += __shfl_xor_sync(0xffffffffu, pl0, 2);
    pl1 += __shfl_xor_sync(0xffffffffu, pl1, 1);
    pl1 += __shfl_xor_sync(0xffffffffu, pl1, 2);
    if ((lane & 3) == 0) {
        w_s[m0 + (lane >> 2)]     = pl0;
        w_s[m0 + 8 + (lane >> 2)] = pl1;
    }
    __syncthreads();

    // ---- softmax per batch over L=64 (warps 0-3; bV shift-invariant) ----
    {
        const bool act = wid < 4;
        const int bb = (wid >> 1) & 1;
        const int li = (wid & 1) * 32 + lane;
        float lv = act ? w_s[bb * 64 + li] : -1e30f;
        float m = lv;
#pragma unroll
        for (int off = 16; off; off >>= 1)
            m = fmaxf(m, __shfl_xor_sync(0xffffffffu, m, off));
        if (act && lane == 0) red_s[wid] = m;
        __syncthreads();
        const float mx = fmaxf(red_s[bb * 2], red_s[bb * 2 + 1]);
        float e = act ? expf(lv - mx) : 0.f;
        float s = e;
#pragma unroll
        for (int off = 16; off; off >>= 1)
            s += __shfl_xor_sync(0xffffffffu, s, off);
        if (act && lane == 0) red_s[4 + wid] = s;
        __syncthreads();
        if (act) w_s[bb * 64 + li] = e / (red_s[4 + bb * 2] + red_s[5 + bb * 2]);
        __syncthreads();
    }

    // ---- context: ctx[bb,d] = sum_l w[bb,l] * (F_hi + F_lo)[bb*64+l, d] ----
    {
        const int d = tid;
#pragma unroll
        for (int bb = 0; bb < 2; ++bb) {
            float cacc = 0.f;
#pragma unroll 8
            for (int l = 0; l < 64; ++l) {
                const uint32_t off = (((uint32_t)(bb * 64 + l)) * PITCH + d) * 2;
                const float hi = __bfloat162float(*(const __nv_bfloat16*)(smem + SA_HI + off));
                const float lo = __bfloat162float(*(const __nv_bfloat16*)(smem + SA_LO + off));
                cacc = fmaf(w_s[bb * 64 + l], hi + lo, cacc);
            }
            if (ctx_out) ctx_out[(size_t)(b0 + bb) * D_SZ + d] = cacc;
        }
        if (w_out && tid < 128) w_out[(size_t)b0 * L_SZ + tid] = w_s[tid];
    }

    __syncthreads();
    if (tid == 0) {
        MBARRIER_INVAL(smem_u + SMBAR);
        MBARRIER_INVAL(smem_u + SMBAR + 8);
    }
}

// ---------------------------------------------------------------------------
extern "C" void kernel_launch(void* const* d_in, const int* in_sizes, int n_in,
                              void* d_out, int out_size)
{
    const float* features = (const float*)d_in[0];
    const float* hidden   = (const float*)d_in[1];
    const float* W1       = (const float*)d_in[2];
    const float* b1       = (const float*)d_in[3];
    const float* W2       = (const float*)d_in[4];
    const float* b2       = (const float*)d_in[5];
    const float* V        = (const float*)d_in[6];
    // d_in[7] = bV: softmax shift-invariant -> no output effect.

    float* out = (float*)d_out;
    float* ctx_out = nullptr;
    float* w_out   = nullptr;
    const int CTX_N = B_SZ * D_SZ;
    const int W_N   = B_SZ * L_SZ;
    if (out_size >= CTX_N + W_N) { ctx_out = out; w_out = out + CTX_N; }
    else if (out_size == CTX_N)  { ctx_out = out; }
    else if (out_size == W_N)    { w_out = out; }
    else                         { ctx_out = out; }

    prep_w1_kernel<<<D_SZ, U_SZ>>>(W1);

    dim3 g1(U_SZ / 64, B_SZ / 64);
    proj_h_kernel<<<g1, 256>>>(hidden, W2, b1, b2);

    cudaFuncSetAttribute(attn_mma_kernel,
                         cudaFuncAttributeMaxDynamicSharedMemorySize, SMEM_TOTAL);
    attn_mma_kernel<<<B_SZ / 2, 256, SMEM_TOTAL>>>(features, V, ctx_out, w_out);
}